// round 4
// baseline (speedup 1.0000x reference)
#include <cuda_runtime.h>
#include <cuda_bf16.h>

// FocalLoss: input [N,C]=[1048576,80] fp32, target [N] int32, gamma=2.
// out[0] = mean_n sum_c -(1-pt)^2 * logpt,  logpt = log_sigmoid(sign*x)
//
// Single fused kernel: grid-stride compute -> per-block double partial ->
// last-block (atomic counter) deterministic final reduction.
// 2 MUFU/elem (EX2 + LG2); pt reciprocal done via Newton on the FMA pipe.

#define N_ROWS   1048576
#define C_CLS    80
#define C4       (C_CLS / 4)           // 20 float4 per row
#define NBLOCKS  1184                  // 148 SMs * 8 CTAs(256)
#define NTHREADS 256

__device__ double g_partials[NBLOCKS];
__device__ unsigned int g_count;       // zero-initialized; self-resets each run

__device__ __forceinline__ float focal_elem(float v, bool is_target) {
    float x  = is_target ? v : -v;
    float ax = fabsf(x);
    float e  = __expf(-ax);                 // MUFU #1 (EX2), e in (0,1]
    float d  = 1.0f + e;                    // (1,2]
    // r = 1/d via Newton on FMA pipe.
    // Linear minimax init for d in [1,2]: r0 = 24/17 - (8/17)*d  (max rel err 1/17)
    float r  = fmaf(d, -0.470588235f, 1.411764706f);
    r = r * fmaf(-d, r, 2.0f);              // err -> (1/17)^2
    r = r * fmaf(-d, r, 2.0f);              // err -> ~1.2e-5
    float L  = __logf(d);                   // MUFU #2 (LG2): ln(1+e)
    float logpt = fminf(x, 0.0f) - L;       // log_sigmoid(x)
    float omp = (x >= 0.0f) ? e * r : r;    // 1 - pt = sigmoid(-x)
    return -(omp * omp) * logpt;            // positive
}

__global__ __launch_bounds__(NTHREADS) void focal_fused_kernel(
    const float* __restrict__ inp,
    const int* __restrict__ tgt,
    float* __restrict__ out)
{
    const unsigned n4 = (unsigned)N_ROWS * C4;      // 20,971,520
    const unsigned stride = gridDim.x * blockDim.x;
    unsigned i = blockIdx.x * blockDim.x + threadIdx.x;

    float fsum = 0.0f;
    const float4* __restrict__ inp4 = (const float4*)inp;

    for (; i < n4; i += stride) {
        unsigned row  = i / (unsigned)C4;           // mul-by-magic
        unsigned col0 = (i - row * (unsigned)C4) * 4u;
        int t = __ldg(&tgt[row]);
        float4 v = __ldg(&inp4[i]);

        fsum += focal_elem(v.x, (int)col0     == t);
        fsum += focal_elem(v.y, (int)col0 + 1 == t);
        fsum += focal_elem(v.z, (int)col0 + 2 == t);
        fsum += focal_elem(v.w, (int)col0 + 3 == t);
    }

    // warp reduce (float), then block reduce in double
    #pragma unroll
    for (int off = 16; off > 0; off >>= 1)
        fsum += __shfl_down_sync(0xFFFFFFFFu, fsum, off);

    __shared__ double s_warp[NTHREADS / 32];
    int lane = threadIdx.x & 31;
    int wid  = threadIdx.x >> 5;
    if (lane == 0) s_warp[wid] = (double)fsum;
    __syncthreads();

    __shared__ bool s_last;
    if (threadIdx.x == 0) {
        double bsum = 0.0;
        #pragma unroll
        for (int w = 0; w < NTHREADS / 32; w++) bsum += s_warp[w];
        g_partials[blockIdx.x] = bsum;
        __threadfence();
        unsigned done = atomicAdd(&g_count, 1u);
        s_last = (done == gridDim.x - 1);
    }
    __syncthreads();

    if (s_last) {
        __threadfence();  // order: see all g_partials published before counter hit max
        __shared__ double s_red[NTHREADS];
        double v = 0.0;
        for (int k = threadIdx.x; k < NBLOCKS; k += NTHREADS)
            v += g_partials[k];
        s_red[threadIdx.x] = v;
        __syncthreads();
        #pragma unroll
        for (int off = NTHREADS / 2; off > 0; off >>= 1) {
            if (threadIdx.x < off) s_red[threadIdx.x] += s_red[threadIdx.x + off];
            __syncthreads();
        }
        if (threadIdx.x == 0) {
            out[0] = (float)(s_red[0] / (double)N_ROWS);
            g_count = 0;   // reset for next graph replay
        }
    }
}

extern "C" void kernel_launch(void* const* d_in, const int* in_sizes, int n_in,
                              void* d_out, int out_size)
{
    const float* inp = (const float*)d_in[0];
    const int* tgt   = (const int*)d_in[1];
    float* out       = (float*)d_out;

    focal_fused_kernel<<<NBLOCKS, NTHREADS>>>(inp, tgt, out);
}

// round 5
// speedup vs baseline: 1.2139x; 1.2139x over previous
#include <cuda_runtime.h>
#include <cuda_bf16.h>

// FocalLoss: input [N,C]=[1048576,80] fp32, target [N] int32, gamma=2.
// out = mean_n sum_c -(1-pt)^2*logpt, pt = sigmoid(sign*x).
//
// Branch-free formulation: loss(x) = (g*r)^2 * ln(d),  g=e^{-x}, d=1+g, r=1/d.
// Main loop assumes every element is non-target (x=-v); a cheap per-row
// correction adds F(v_t) - F(-v_t) for the target element.
// Accumulated in log2 units; *ln2 applied once at the end.

#define N_ROWS   1048576
#define C_CLS    80
#define NBLOCKS  1184
#define NTHREADS 256
#define L2E      1.44269504f
#define LN2      0.6931471805599453

__device__ double g_partials[NBLOCKS];
__device__ unsigned int g_count;

__device__ __forceinline__ float ex2f_(float x) {
    float y; asm("ex2.approx.f32 %0, %1;" : "=f"(y) : "f"(x)); return y;
}
__device__ __forceinline__ float lg2f_(float x) {
    float y; asm("lg2.approx.f32 %0, %1;" : "=f"(y) : "f"(x)); return y;
}

// loss(x)/ln2 = (g*r)^2 * log2(1+g),  g = e^{-x}
__device__ __forceinline__ float focal_l2(float x) {
    float g = ex2f_(x * -L2E);                    // FMUL + MUFU.EX2
    float d = 1.0f + g;                           // FADD
    float r = __uint_as_float(0x7EF311C3u - __float_as_uint(d));  // IADD (alu pipe)
    r = r * fmaf(-d, r, 2.0f);                    // FFMA + FMUL
    r = r * fmaf(-d, r, 2.0f);                    // FFMA + FMUL
    float p = g * r;                              // sigma(-x)
    return (p * p) * lg2f_(d);                    // FMUL + MUFU.LG2 + FMUL
}

__global__ __launch_bounds__(NTHREADS) void focal_fused_kernel(
    const float* __restrict__ inp,
    const int* __restrict__ tgt,
    float* __restrict__ out)
{
    const unsigned nthreads = gridDim.x * blockDim.x;      // 303104
    const unsigned gid = blockIdx.x * blockDim.x + threadIdx.x;

    float fs0 = 0.0f, fs1 = 0.0f;

    // Phase A: per-row target correction: + F(v_t) - F(-v_t)
    for (unsigned row = gid; row < (unsigned)N_ROWS; row += nthreads) {
        int t = __ldg(&tgt[row]);
        float v = __ldg(&inp[row * (unsigned)C_CLS + (unsigned)t]);
        fs0 += focal_l2(v) - focal_l2(-v);
    }

    // Phase B: all elements as non-target (x = -v), two independent streams
    const float4* __restrict__ inp4 = (const float4*)inp;
    const unsigned half = ((unsigned)N_ROWS * (unsigned)C_CLS / 4u) / 2u; // 10,485,760
    for (unsigned j = gid; j < half; j += nthreads) {
        float4 a = __ldg(&inp4[j]);
        float4 b = __ldg(&inp4[j + half]);
        fs0 += focal_l2(-a.x);
        fs1 += focal_l2(-a.y);
        fs0 += focal_l2(-a.z);
        fs1 += focal_l2(-a.w);
        fs0 += focal_l2(-b.x);
        fs1 += focal_l2(-b.y);
        fs0 += focal_l2(-b.z);
        fs1 += focal_l2(-b.w);
    }

    float fsum = fs0 + fs1;

    #pragma unroll
    for (int off = 16; off > 0; off >>= 1)
        fsum += __shfl_down_sync(0xFFFFFFFFu, fsum, off);

    __shared__ double s_warp[NTHREADS / 32];
    int lane = threadIdx.x & 31;
    int wid  = threadIdx.x >> 5;
    if (lane == 0) s_warp[wid] = (double)fsum;
    __syncthreads();

    __shared__ bool s_last;
    if (threadIdx.x == 0) {
        double bsum = 0.0;
        #pragma unroll
        for (int w = 0; w < NTHREADS / 32; w++) bsum += s_warp[w];
        g_partials[blockIdx.x] = bsum;
        __threadfence();
        unsigned done = atomicAdd(&g_count, 1u);
        s_last = (done == gridDim.x - 1);
    }
    __syncthreads();

    if (s_last) {
        __threadfence();
        __shared__ double s_red[NTHREADS];
        double v = 0.0;
        for (int k = threadIdx.x; k < NBLOCKS; k += NTHREADS)
            v += g_partials[k];
        s_red[threadIdx.x] = v;
        __syncthreads();
        #pragma unroll
        for (int off = NTHREADS / 2; off > 0; off >>= 1) {
            if (threadIdx.x < off) s_red[threadIdx.x] += s_red[threadIdx.x + off];
            __syncthreads();
        }
        if (threadIdx.x == 0) {
            out[0] = (float)(s_red[0] * LN2 / (double)N_ROWS);
            g_count = 0;
        }
    }
}

extern "C" void kernel_launch(void* const* d_in, const int* in_sizes, int n_in,
                              void* d_out, int out_size)
{
    const float* inp = (const float*)d_in[0];
    const int* tgt   = (const int*)d_in[1];
    float* out       = (float*)d_out;

    focal_fused_kernel<<<NBLOCKS, NTHREADS>>>(inp, tgt, out);
}

// round 6
// speedup vs baseline: 1.2431x; 1.0241x over previous
#include <cuda_runtime.h>
#include <cuda_bf16.h>

// FocalLoss: input [N,C]=[1048576,80] fp32, target [N] int32, gamma=2.
// out = mean_n sum_c -(1-pt)^2*logpt, pt = sigmoid(sign*x).
//
// Warp-tile layout: each warp iteration processes 8 rows (160 float4s) with
// 5 coalesced warp-wide LDG.128. Targets fetched once per tile (32B LDG) and
// broadcast via shfl. Sign handled by selecting +/-log2(e) into the scale FMUL.
// loss(x)/ln2 = (g/(1+g))^2 * log2(1+g),  g = e^{-x} = ex2(-x*log2e).
// 2 MUFU/elem; reciprocal via magic seed + 2 Newton steps (FMA/ALU pipes).

#define N_ROWS   1048576
#define C_CLS    80
#define ROWS_PER_TILE 8
#define F4_PER_TILE   160          // 8 rows * 20 float4
#define N_TILES  (N_ROWS / ROWS_PER_TILE)   // 131072
#define NBLOCKS  1184
#define NTHREADS 256
#define WARPS_PER_BLOCK (NTHREADS / 32)
#define L2E      1.44269504f
#define LN2      0.6931471805599453

__device__ double g_partials[NBLOCKS];
__device__ unsigned int g_count;

__device__ __forceinline__ float ex2f_(float x) {
    float y; asm("ex2.approx.f32 %0, %1;" : "=f"(y) : "f"(x)); return y;
}
__device__ __forceinline__ float lg2f_(float x) {
    float y; asm("lg2.approx.f32 %0, %1;" : "=f"(y) : "f"(x)); return y;
}

// acc += loss(x)/ln2 where x = v if is_t else -v.
// s = is_t ? +L2E : -L2E (so g = ex2(-x*L2E) = ex2(v * -s)).
__device__ __forceinline__ void focal_acc(float v, bool is_t, float& acc) {
    float s = is_t ? -L2E : L2E;
    float g = ex2f_(v * s);                 // e^{-x}
    float d = 1.0f + g;
    float r = __uint_as_float(0x7EF311C3u - __float_as_uint(d));
    r = r * fmaf(-d, r, 2.0f);
    r = r * fmaf(-d, r, 2.0f);
    float p = g * r;                        // sigma(-x) = 1 - pt
    acc = fmaf(p * p, lg2f_(d), acc);
}

__global__ __launch_bounds__(NTHREADS) void focal_fused_kernel(
    const float* __restrict__ inp,
    const int* __restrict__ tgt,
    float* __restrict__ out)
{
    const unsigned lane   = threadIdx.x & 31u;
    const unsigned gwarp  = blockIdx.x * WARPS_PER_BLOCK + (threadIdx.x >> 5);
    const unsigned nwarps = gridDim.x * WARPS_PER_BLOCK;   // 9472

    const float4* __restrict__ inp4 = (const float4*)inp;

    float fs0 = 0.0f, fs1 = 0.0f;

    for (unsigned tile = gwarp; tile < (unsigned)N_TILES; tile += nwarps) {
        // one coalesced 32B load of the tile's 8 targets; lane holds tgt[lane&7]
        int tmy = __ldg(&tgt[tile * ROWS_PER_TILE + (lane & 7u)]);
        unsigned base = tile * (unsigned)F4_PER_TILE;

        #pragma unroll
        for (int k = 0; k < 5; k++) {
            unsigned idx  = (unsigned)k * 32u + lane;   // 0..159
            unsigned row  = idx / 20u;                  // magic-mul
            unsigned col0 = (idx - row * 20u) * 4u;
            int t = __shfl_sync(0xFFFFFFFFu, tmy, (int)row);
            float4 v = __ldg(&inp4[base + idx]);

            int dt = t - (int)col0;                     // match if dt in [0,4)
            float& acc = (k & 1) ? fs1 : fs0;
            focal_acc(v.x, dt == 0, acc);
            focal_acc(v.y, dt == 1, acc);
            focal_acc(v.z, dt == 2, acc);
            focal_acc(v.w, dt == 3, acc);
        }
    }

    float fsum = fs0 + fs1;

    #pragma unroll
    for (int off = 16; off > 0; off >>= 1)
        fsum += __shfl_down_sync(0xFFFFFFFFu, fsum, off);

    __shared__ double s_warp[WARPS_PER_BLOCK];
    int wid = threadIdx.x >> 5;
    if (lane == 0) s_warp[wid] = (double)fsum;
    __syncthreads();

    __shared__ bool s_last;
    if (threadIdx.x == 0) {
        double bsum = 0.0;
        #pragma unroll
        for (int w = 0; w < WARPS_PER_BLOCK; w++) bsum += s_warp[w];
        g_partials[blockIdx.x] = bsum;
        __threadfence();
        unsigned done = atomicAdd(&g_count, 1u);
        s_last = (done == gridDim.x - 1);
    }
    __syncthreads();

    if (s_last) {
        __threadfence();
        __shared__ double s_red[NTHREADS];
        double v = 0.0;
        for (int k = threadIdx.x; k < NBLOCKS; k += NTHREADS)
            v += g_partials[k];
        s_red[threadIdx.x] = v;
        __syncthreads();
        #pragma unroll
        for (int off = NTHREADS / 2; off > 0; off >>= 1) {
            if (threadIdx.x < off) s_red[threadIdx.x] += s_red[threadIdx.x + off];
            __syncthreads();
        }
        if (threadIdx.x == 0) {
            out[0] = (float)(s_red[0] * LN2 / (double)N_ROWS);
            g_count = 0;
        }
    }
}

extern "C" void kernel_launch(void* const* d_in, const int* in_sizes, int n_in,
                              void* d_out, int out_size)
{
    const float* inp = (const float*)d_in[0];
    const int* tgt   = (const int*)d_in[1];
    float* out       = (float*)d_out;

    focal_fused_kernel<<<NBLOCKS, NTHREADS>>>(inp, tgt, out);
}

// round 7
// speedup vs baseline: 1.3967x; 1.1236x over previous
#include <cuda_runtime.h>
#include <cuda_bf16.h>

// FocalLoss: input [N,C]=[1048576,80] fp32, target [N] int32, gamma=2.
// out = mean_n sum_c -(1-pt)^2*logpt, pt = sigmoid(sign*x).
//
// Warp-tile layout: each warp iteration processes 8 rows (160 float4s) with
// 5 coalesced warp-wide LDG.128. Targets fetched once per tile (32B LDG) and
// broadcast via shfl. Sign handled by selecting +/-log2(e) into the scale FMUL.
// loss(x)/ln2 = (g/(1+g))^2 * log2(1+g),  g = e^{-x} = ex2(-x*log2e).
//
// R7 change: NBLOCKS 1184 -> 888 (148 SMs x 6 CTAs at regs=40) to eliminate
// the 2-wave launch quantization seen in R6.

#define N_ROWS   1048576
#define C_CLS    80
#define ROWS_PER_TILE 8
#define F4_PER_TILE   160          // 8 rows * 20 float4
#define N_TILES  (N_ROWS / ROWS_PER_TILE)   // 131072
#define NBLOCKS  888               // 148 SMs * 6 resident CTAs -> single wave
#define NTHREADS 256
#define WARPS_PER_BLOCK (NTHREADS / 32)
#define L2E      1.44269504f
#define LN2      0.6931471805599453

__device__ double g_partials[NBLOCKS];
__device__ unsigned int g_count;

__device__ __forceinline__ float ex2f_(float x) {
    float y; asm("ex2.approx.f32 %0, %1;" : "=f"(y) : "f"(x)); return y;
}
__device__ __forceinline__ float lg2f_(float x) {
    float y; asm("lg2.approx.f32 %0, %1;" : "=f"(y) : "f"(x)); return y;
}

// acc += loss(x)/ln2 where x = v if is_t else -v.
__device__ __forceinline__ void focal_acc(float v, bool is_t, float& acc) {
    float s = is_t ? -L2E : L2E;
    float g = ex2f_(v * s);                 // e^{-x}
    float d = 1.0f + g;
    float r = __uint_as_float(0x7EF311C3u - __float_as_uint(d));
    r = r * fmaf(-d, r, 2.0f);
    r = r * fmaf(-d, r, 2.0f);
    float p = g * r;                        // sigma(-x) = 1 - pt
    acc = fmaf(p * p, lg2f_(d), acc);
}

__global__ __launch_bounds__(NTHREADS) void focal_fused_kernel(
    const float* __restrict__ inp,
    const int* __restrict__ tgt,
    float* __restrict__ out)
{
    const unsigned lane   = threadIdx.x & 31u;
    const unsigned gwarp  = blockIdx.x * WARPS_PER_BLOCK + (threadIdx.x >> 5);
    const unsigned nwarps = gridDim.x * WARPS_PER_BLOCK;   // 7104

    const float4* __restrict__ inp4 = (const float4*)inp;

    float fs0 = 0.0f, fs1 = 0.0f;

    for (unsigned tile = gwarp; tile < (unsigned)N_TILES; tile += nwarps) {
        int tmy = __ldg(&tgt[tile * ROWS_PER_TILE + (lane & 7u)]);
        unsigned base = tile * (unsigned)F4_PER_TILE;

        #pragma unroll
        for (int k = 0; k < 5; k++) {
            unsigned idx  = (unsigned)k * 32u + lane;   // 0..159
            unsigned row  = idx / 20u;                  // magic-mul
            unsigned col0 = (idx - row * 20u) * 4u;
            int t = __shfl_sync(0xFFFFFFFFu, tmy, (int)row);
            float4 v = __ldg(&inp4[base + idx]);

            int dt = t - (int)col0;                     // match if dt in [0,4)
            float& acc = (k & 1) ? fs1 : fs0;
            focal_acc(v.x, dt == 0, acc);
            focal_acc(v.y, dt == 1, acc);
            focal_acc(v.z, dt == 2, acc);
            focal_acc(v.w, dt == 3, acc);
        }
    }

    float fsum = fs0 + fs1;

    #pragma unroll
    for (int off = 16; off > 0; off >>= 1)
        fsum += __shfl_down_sync(0xFFFFFFFFu, fsum, off);

    __shared__ double s_warp[WARPS_PER_BLOCK];
    int wid = threadIdx.x >> 5;
    if (lane == 0) s_warp[wid] = (double)fsum;
    __syncthreads();

    __shared__ bool s_last;
    if (threadIdx.x == 0) {
        double bsum = 0.0;
        #pragma unroll
        for (int w = 0; w < WARPS_PER_BLOCK; w++) bsum += s_warp[w];
        g_partials[blockIdx.x] = bsum;
        __threadfence();
        unsigned done = atomicAdd(&g_count, 1u);
        s_last = (done == gridDim.x - 1);
    }
    __syncthreads();

    if (s_last) {
        __threadfence();
        __shared__ double s_red[NTHREADS];
        double v = 0.0;
        for (int k = threadIdx.x; k < NBLOCKS; k += NTHREADS)
            v += g_partials[k];
        s_red[threadIdx.x] = v;
        __syncthreads();
        #pragma unroll
        for (int off = NTHREADS / 2; off > 0; off >>= 1) {
            if (threadIdx.x < off) s_red[threadIdx.x] += s_red[threadIdx.x + off];
            __syncthreads();
        }
        if (threadIdx.x == 0) {
            out[0] = (float)(s_red[0] * LN2 / (double)N_ROWS);
            g_count = 0;
        }
    }
}

extern "C" void kernel_launch(void* const* d_in, const int* in_sizes, int n_in,
                              void* d_out, int out_size)
{
    const float* inp = (const float*)d_in[0];
    const int* tgt   = (const int*)d_in[1];
    float* out       = (float*)d_out;

    focal_fused_kernel<<<NBLOCKS, NTHREADS>>>(inp, tgt, out);
}

// round 8
// speedup vs baseline: 1.4484x; 1.0370x over previous
#include <cuda_runtime.h>
#include <cuda_bf16.h>

// FocalLoss: input [N,C]=[1048576,80] fp32, target [N] int32, gamma=2.
// out = mean_n sum_c -(1-pt)^2*logpt, pt = sigmoid(sign*x).
//
// R8: pure-streaming main loop (no target logic), per-tile correction via
// L2-hit gather of the 1 target element per row, done by the same warp that
// just streamed those lines. loss(x)/ln2 = (g/(1+g))^2*log2(1+g), g=e^{-x}.
// Non-target: x=-v -> g=ex2(v*log2e). Target: g=ex2(-v*log2e).

#define N_ROWS   1048576
#define C_CLS    80
#define ROWS_PER_TILE 32
#define F4_PER_TILE   640          // 32 rows * 20 float4
#define N_TILES  (N_ROWS / ROWS_PER_TILE)   // 32768
#define NBLOCKS  1184              // 148 SMs * 8 CTAs, single wave at regs<=32
#define NTHREADS 256
#define WARPS_PER_BLOCK (NTHREADS / 32)
#define L2E      1.44269504f
#define LN2      0.6931471805599453

__device__ double g_partials[NBLOCKS];
__device__ unsigned int g_count;

__device__ __forceinline__ float ex2f_(float x) {
    float y; asm("ex2.approx.f32 %0, %1;" : "=f"(y) : "f"(x)); return y;
}
__device__ __forceinline__ float lg2f_(float x) {
    float y; asm("lg2.approx.f32 %0, %1;" : "=f"(y) : "f"(x)); return y;
}

// core(w) = (g/(1+g))^2 * log2(1+g) with g = 2^w.
// Non-target element v: w = v*L2E. Target element v: w = -v*L2E.
__device__ __forceinline__ float focal_core(float w) {
    float g = ex2f_(w);
    float d = 1.0f + g;
    float r = __uint_as_float(0x7EF311C3u - __float_as_uint(d));  // ~5% seed
    r = r * fmaf(-d, r, 2.0f);              // -> ~2.5e-3
    r = r * fmaf(-d, r, 2.0f);              // -> ~6e-6
    float p = g * r;                        // sigma(-x)
    return (p * p) * lg2f_(d);
}

__global__ __launch_bounds__(NTHREADS, 8) void focal_fused_kernel(
    const float* __restrict__ inp,
    const int* __restrict__ tgt,
    float* __restrict__ out)
{
    const unsigned lane   = threadIdx.x & 31u;
    const unsigned gwarp  = blockIdx.x * WARPS_PER_BLOCK + (threadIdx.x >> 5);
    const unsigned nwarps = gridDim.x * WARPS_PER_BLOCK;   // 9472

    const float4* __restrict__ inp4 = (const float4*)inp;

    float fs0 = 0.0f, fs1 = 0.0f;

    for (unsigned tile = gwarp; tile < (unsigned)N_TILES; tile += nwarps) {
        const unsigned row0 = tile * ROWS_PER_TILE;
        const unsigned base = tile * (unsigned)F4_PER_TILE + lane;

        // Main: stream 640 float4s, everything treated as non-target.
        #pragma unroll 4
        for (unsigned k = 0; k < 20u; k++) {
            float4 v = __ldg(&inp4[base + k * 32u]);
            fs0 += focal_core(v.x * L2E);
            fs1 += focal_core(v.y * L2E);
            fs0 += focal_core(v.z * L2E);
            fs1 += focal_core(v.w * L2E);
        }

        // Correction: lane fixes row (row0+lane). Lines just streamed -> L2 hit.
        int   t  = __ldg(&tgt[row0 + lane]);
        float tv = __ldg(&inp[(row0 + lane) * (unsigned)C_CLS + (unsigned)t]);
        fs0 += focal_core(tv * -L2E) - focal_core(tv * L2E);
    }

    float fsum = fs0 + fs1;

    #pragma unroll
    for (int off = 16; off > 0; off >>= 1)
        fsum += __shfl_down_sync(0xFFFFFFFFu, fsum, off);

    __shared__ double s_warp[WARPS_PER_BLOCK];
    int wid = threadIdx.x >> 5;
    if (lane == 0) s_warp[wid] = (double)fsum;
    __syncthreads();

    __shared__ bool s_last;
    if (threadIdx.x == 0) {
        double bsum = 0.0;
        #pragma unroll
        for (int w = 0; w < WARPS_PER_BLOCK; w++) bsum += s_warp[w];
        g_partials[blockIdx.x] = bsum;
        __threadfence();
        unsigned done = atomicAdd(&g_count, 1u);
        s_last = (done == gridDim.x - 1);
    }
    __syncthreads();

    if (s_last) {
        __threadfence();
        __shared__ double s_red[NTHREADS];
        double v = 0.0;
        for (int k = threadIdx.x; k < NBLOCKS; k += NTHREADS)
            v += g_partials[k];
        s_red[threadIdx.x] = v;
        __syncthreads();
        #pragma unroll
        for (int off = NTHREADS / 2; off > 0; off >>= 1) {
            if (threadIdx.x < off) s_red[threadIdx.x] += s_red[threadIdx.x + off];
            __syncthreads();
        }
        if (threadIdx.x == 0) {
            out[0] = (float)(s_red[0] * LN2 / (double)N_ROWS);
            g_count = 0;
        }
    }
}

extern "C" void kernel_launch(void* const* d_in, const int* in_sizes, int n_in,
                              void* d_out, int out_size)
{
    const float* inp = (const float*)d_in[0];
    const int* tgt   = (const int*)d_in[1];
    float* out       = (float*)d_out;

    focal_fused_kernel<<<NBLOCKS, NTHREADS>>>(inp, tgt, out);
}